// round 10
// baseline (speedup 1.0000x reference)
#include <cuda_runtime.h>
#include <cuda_bf16.h>
#include <cstdint>

// TransINT scoring, single-pass quadratic form, TWO WARPS PER SAMPLE.
//   re = heads[rel2head[r]] * rel2mult[r]        (r = pos_r; neg_r unused)
//   s_pos = ent[ph] + re - ent[pt];  s_neg = ent[nh] + re - ent[nt]
//   A = bases[r] (2 x 256); c = ATA^{-1} (A.s)
//   exact-solution identity: ||s - A^T c||^2 = s.s - c.(A.s)
// out[0:B) = pos, out[B:2B) = neg (float32)
//
// Warp pair (2k, 2k+1) handles sample k of the block: warp half=0 owns dims
// [0,128), half=1 owns [128,256). Each lane loads ONE float4 per vector
// (7 loads, 28 live floats) -> ~40 regs -> 6 blocks/SM (48 warps, 75% occ)
// vs 5 blocks at the 1-warp/sample layout. Partial 9-value reductions meet
// in shared memory; even warp's lane 0 finalizes.

#define D 256
#define SAMPLES_PER_BLOCK 4   // 8 warps / 2

__global__ __launch_bounds__(256, 6)
void transint_kernel(const int* __restrict__ pos_h,
                     const int* __restrict__ pos_t,
                     const int* __restrict__ pos_r,
                     const int* __restrict__ neg_h,
                     const int* __restrict__ neg_t,
                     const float* __restrict__ ent_emb,   // E x D
                     const float* __restrict__ heads,     // K x D
                     const float* __restrict__ bases,     // R x 2 x D
                     const int* __restrict__ rel2head,
                     const float* __restrict__ rel2mult,
                     float* __restrict__ out,
                     int B)
{
    const int warp = threadIdx.x >> 5;
    const int lane = threadIdx.x & 31;
    const int pair = warp >> 1;   // 0..3 : sample slot within block
    const int half = warp & 1;    // 0: dims [0,128), 1: dims [128,256)

    int s = blockIdx.x * SAMPLES_PER_BLOCK + pair;
    const bool valid = (s < B);
    if (!valid) s = 0;            // safe dummy work; no early return (bar sync)

    // Per-sample indices (uniform across warp; broadcast loads)
    const int ph = pos_h[s];
    const int pt = pos_t[s];
    const int r  = pos_r[s];
    const int nh = neg_h[s];
    const int nt = neg_t[s];
    const int hd = rel2head[r];
    const float mult = rel2mult[r];

    // float4 index within the 64-float4 row: this warp's 512B contiguous half
    const int v = lane + (half << 5);

    const float4* __restrict__ Eph = (const float4*)(ent_emb + (size_t)ph * D);
    const float4* __restrict__ Ept = (const float4*)(ent_emb + (size_t)pt * D);
    const float4* __restrict__ Enh = (const float4*)(ent_emb + (size_t)nh * D);
    const float4* __restrict__ Ent = (const float4*)(ent_emb + (size_t)nt * D);
    const float4* __restrict__ Hd  = (const float4*)(heads   + (size_t)hd * D);
    const float4* __restrict__ A0p = (const float4*)(bases   + (size_t)r * 2 * D);
    const float4* __restrict__ A1p = (const float4*)(bases   + (size_t)r * 2 * D + D);

    // 7 loads, all independent and issued up-front (28 live floats)
    const float4 hp = Eph[v];
    const float4 tp = Ept[v];
    const float4 hn = Enh[v];
    const float4 tn = Ent[v];
    const float4 re = Hd[v];
    const float4 a0 = A0p[v];
    const float4 a1 = A1p[v];

    // 9 streamed accumulators over this lane's 4 dims
    float aa = 0.f, ab = 0.f, dd = 0.f;
    float as0p = 0.f, as1p = 0.f, ssp = 0.f;
    float as0n = 0.f, as1n = 0.f, ssn = 0.f;
    {
        const float* hpp = (const float*)&hp;
        const float* tpp = (const float*)&tp;
        const float* hnp = (const float*)&hn;
        const float* tnp = (const float*)&tn;
        const float* rep = (const float*)&re;
        const float* a0p = (const float*)&a0;
        const float* a1p = (const float*)&a1;
        #pragma unroll
        for (int i = 0; i < 4; i++) {
            const float rr = rep[i] * mult;
            const float sv = hpp[i] + rr - tpp[i];
            const float nv = hnp[i] + rr - tnp[i];
            const float A0 = a0p[i], A1 = a1p[i];
            aa   = fmaf(A0, A0, aa);
            ab   = fmaf(A0, A1, ab);
            dd   = fmaf(A1, A1, dd);
            as0p = fmaf(A0, sv, as0p);
            as1p = fmaf(A1, sv, as1p);
            ssp  = fmaf(sv, sv, ssp);
            as0n = fmaf(A0, nv, as0n);
            as1n = fmaf(A1, nv, as1n);
            ssn  = fmaf(nv, nv, ssn);
        }
    }

    // Fused butterfly allreduce of 9 scalars within the warp
    #pragma unroll
    for (int m = 16; m > 0; m >>= 1) {
        aa   += __shfl_xor_sync(0xffffffffu, aa,   m);
        ab   += __shfl_xor_sync(0xffffffffu, ab,   m);
        dd   += __shfl_xor_sync(0xffffffffu, dd,   m);
        as0p += __shfl_xor_sync(0xffffffffu, as0p, m);
        as1p += __shfl_xor_sync(0xffffffffu, as1p, m);
        ssp  += __shfl_xor_sync(0xffffffffu, ssp,  m);
        as0n += __shfl_xor_sync(0xffffffffu, as0n, m);
        as1n += __shfl_xor_sync(0xffffffffu, as1n, m);
        ssn  += __shfl_xor_sync(0xffffffffu, ssn,  m);
    }

    // Cross-warp exchange: 9 partials per warp
    __shared__ float red[SAMPLES_PER_BLOCK][2][12];  // padded
    if (lane == 0) {
        float* dst = red[pair][half];
        dst[0] = aa;   dst[1] = ab;   dst[2] = dd;
        dst[3] = as0p; dst[4] = as1p; dst[5] = ssp;
        dst[6] = as0n; dst[7] = as1n; dst[8] = ssn;
    }
    __syncthreads();

    if (half == 0 && lane == 0 && valid) {
        const float* p0 = red[pair][0];
        const float* p1 = red[pair][1];
        const float r_aa   = p0[0] + p1[0];
        const float r_ab   = p0[1] + p1[1];
        const float r_dd   = p0[2] + p1[2];
        const float r_as0p = p0[3] + p1[3];
        const float r_as1p = p0[4] + p1[4];
        const float r_ssp  = p0[5] + p1[5];
        const float r_as0n = p0[6] + p1[6];
        const float r_as1n = p0[7] + p1[7];
        const float r_ssn  = p0[8] + p1[8];

        const float det = r_aa * r_dd - r_ab * r_ab;
        float scp, scn;
        if (det != 0.0f) {
            // exact normal-equation solve -> ||proj||^2 = ss - c . As
            const float inv_det = 1.0f / det;
            const float c0p = ( r_dd * r_as0p - r_ab * r_as1p) * inv_det;
            const float c1p = (-r_ab * r_as0p + r_aa * r_as1p) * inv_det;
            const float c0n = ( r_dd * r_as0n - r_ab * r_as1n) * inv_det;
            const float c1n = (-r_ab * r_as0n + r_aa * r_as1n) * inv_det;
            scp = r_ssp - c0p * r_as0p - c1p * r_as1p;
            scn = r_ssn - c0n * r_as0n - c1n * r_as1n;
        } else {
            // fallback c = As / aa is NOT the exact solution -> full quadratic
            const float inv_a = 1.0f / r_aa;
            const float c0p = r_as0p * inv_a, c1p = r_as1p * inv_a;
            const float c0n = r_as0n * inv_a, c1n = r_as1n * inv_a;
            scp = r_ssp - 2.0f * (c0p * r_as0p + c1p * r_as1p)
                + c0p * c0p * r_aa + 2.0f * c0p * c1p * r_ab + c1p * c1p * r_dd;
            scn = r_ssn - 2.0f * (c0n * r_as0n + c1n * r_as1n)
                + c0n * c0n * r_aa + 2.0f * c0n * c1n * r_ab + c1n * c1n * r_dd;
        }
        out[s]     = scp;
        out[B + s] = scn;
    }
}

extern "C" void kernel_launch(void* const* d_in, const int* in_sizes, int n_in,
                              void* d_out, int out_size) {
    const int*   pos_h    = (const int*)  d_in[0];
    const int*   pos_t    = (const int*)  d_in[1];
    const int*   pos_r    = (const int*)  d_in[2];
    const int*   neg_h    = (const int*)  d_in[3];
    const int*   neg_t    = (const int*)  d_in[4];
    // d_in[5] = neg_r (unused by the reference)
    const float* ent_emb  = (const float*)d_in[6];
    const float* heads    = (const float*)d_in[7];
    const float* bases    = (const float*)d_in[8];
    const int*   rel2head = (const int*)  d_in[9];
    const float* rel2mult = (const float*)d_in[10];
    float* out = (float*)d_out;

    const int B = in_sizes[0];
    const int blocks = (B + SAMPLES_PER_BLOCK - 1) / SAMPLES_PER_BLOCK;
    transint_kernel<<<blocks, 256>>>(
        pos_h, pos_t, pos_r, neg_h, neg_t,
        ent_emb, heads, bases, rel2head, rel2mult, out, B);
}